// round 13
// baseline (speedup 1.0000x reference)
#include <cuda_runtime.h>
#include <cstdint>

// Problem constants: B=4, N=512, E=64
#define NROWS 2048          // B*N
#define EDIM  64
#define CDIM  4096          // E*E

// Single dynamic shared memory symbol (shared across all kernels in this TU)
extern __shared__ char dyn_smem[];

// Scratch
__device__ float g_X[NROWS * EDIM];   // left gated activations  [row][d1]
__device__ float g_Y[NROWS * EDIM];   // right gated activations [row][d2]
__device__ float g_Wt[EDIM * CDIM];   // Wt[d1][d2*64+o] = Wc[o][d1*64+d2]
__device__ float g_T[NROWS * CDIM];   // T[row][d2*64+o]

// ---------------------------------------------------------------------------
// Packed fp32x2 helpers
// ---------------------------------------------------------------------------
__device__ __forceinline__ unsigned long long bcast2(float x) {
    unsigned long long r;
    asm("mov.b64 %0, {%1, %1};" : "=l"(r) : "f"(x));
    return r;
}
__device__ __forceinline__ void fma2(unsigned long long& d,
                                     unsigned long long a,
                                     unsigned long long b) {
    asm("fma.rn.f32x2 %0, %1, %2, %3;" : "=l"(d) : "l"(a), "l"(b), "l"(d));
}
__device__ __forceinline__ float2 unpk(unsigned long long v) {
    float2 f;
    asm("mov.b64 {%0, %1}, %2;" : "=f"(f.x), "=f"(f.y) : "l"(v));
    return f;
}

// ---------------------------------------------------------------------------
// Stage A: LayerNorm + two gated projections. 1 block per row, 64 threads.
// ---------------------------------------------------------------------------
__global__ void prep_kernel(const float* __restrict__ emb,
                            const float* __restrict__ g,
                            const float* __restrict__ be,
                            const float* __restrict__ W1,
                            const float* __restrict__ b1,
                            const float* __restrict__ W2,
                            const float* __restrict__ b2)
{
    __shared__ float hsh[64];
    __shared__ float w1s[64 * 65];
    __shared__ float w2s[64 * 65];

    const int row = blockIdx.x;
    const int t   = threadIdx.x;

    for (int i = 0; i < 64; i++) {
        w1s[t * 65 + i] = W1[i * 64 + t];
        w2s[t * 65 + i] = W2[i * 64 + t];
    }

    float v = emb[row * 64 + t];
    hsh[t] = v;
    __syncthreads();

    float s = 0.f;
    #pragma unroll
    for (int d = 0; d < 64; d++) s += hsh[d];
    float mu = s * (1.0f / 64.0f);

    float vs = 0.f;
    #pragma unroll
    for (int d = 0; d < 64; d++) { float z = hsh[d] - mu; vs += z * z; }
    float rstd = rsqrtf(vs * (1.0f / 64.0f) + 1e-5f);

    float h = (v - mu) * rstd * g[t] + be[t];
    __syncthreads();
    hsh[t] = h;
    __syncthreads();

    float p1 = b1[t], p2 = b2[t];
    #pragma unroll
    for (int d = 0; d < 64; d++) {
        float hd = hsh[d];
        p1 += hd * w1s[d * 65 + t];
        p2 += hd * w2s[d * 65 + t];
    }
    g_X[row * 64 + t] = h * p1;
    g_Y[row * 64 + t] = h * p2;
}

// ---------------------------------------------------------------------------
// Stage C: Wt[d1*4096 + d2*64 + o] = Wc[o*4096 + d1*64 + d2]
// ---------------------------------------------------------------------------
__global__ void wt_kernel(const float* __restrict__ Wc)
{
    int i = blockIdx.x * blockDim.x + threadIdx.x;   // 0 .. 262143
    int o    = i & 63;
    int rest = i >> 6;          // d1*64 + d2
    g_Wt[i] = Wc[o * 4096 + rest];
}

// ---------------------------------------------------------------------------
// Stage B: T = X @ Wt  ([2048 x 64] * [64 x 4096]) -> g_T[row][d2*64+o]
// Packed f32x2 accumulation (R9 version, passing).
// ---------------------------------------------------------------------------
__global__ void __launch_bounds__(256) t_kernel()
{
    float* smem = reinterpret_cast<float*>(dyn_smem);
    float* xs = smem;             // [64 d1][64 r]
    float* ws = smem + 64 * 64;   // [64 d1][256 c]

    const int cb  = blockIdx.x;
    const int rb  = blockIdx.y;
    const int tid = threadIdx.x;

    if (tid < 64) {
        const float4* src = reinterpret_cast<const float4*>(g_X + (rb * 64 + tid) * 64);
        #pragma unroll
        for (int c4 = 0; c4 < 16; c4++) {
            float4 v = src[c4];
            xs[(4 * c4 + 0) * 64 + tid] = v.x;
            xs[(4 * c4 + 1) * 64 + tid] = v.y;
            xs[(4 * c4 + 2) * 64 + tid] = v.z;
            xs[(4 * c4 + 3) * 64 + tid] = v.w;
        }
    }
    #pragma unroll
    for (int it = 0; it < 16; it++) {
        int idx = it * 256 + tid;
        int d1  = idx >> 6;
        int c4  = idx & 63;
        reinterpret_cast<float4*>(ws + d1 * 256)[c4] =
            reinterpret_cast<const float4*>(g_Wt + d1 * 4096 + cb * 256)[c4];
    }
    __syncthreads();

    const int tx = tid & 31;
    const int ty = tid >> 5;

    unsigned long long acc[8][4];
    #pragma unroll
    for (int r = 0; r < 8; r++)
        #pragma unroll
        for (int p = 0; p < 4; p++) acc[r][p] = 0ull;

    #pragma unroll 4
    for (int d1 = 0; d1 < 64; d1++) {
        const float* xrow = xs + d1 * 64 + ty * 8;
        float4 a0 = reinterpret_cast<const float4*>(xrow)[0];
        float4 a1 = reinterpret_cast<const float4*>(xrow)[1];
        const float* wrow = ws + d1 * 256;
        ulonglong2 wA = *reinterpret_cast<const ulonglong2*>(wrow + tx * 4);
        ulonglong2 wB = *reinterpret_cast<const ulonglong2*>(wrow + 128 + tx * 4);
        unsigned long long tv[4] = {wA.x, wA.y, wB.x, wB.y};
        float av[8] = {a0.x, a0.y, a0.z, a0.w, a1.x, a1.y, a1.z, a1.w};
        #pragma unroll
        for (int r = 0; r < 8; r++) {
            unsigned long long yb = bcast2(av[r]);
            #pragma unroll
            for (int p = 0; p < 4; p++) fma2(acc[r][p], yb, tv[p]);
        }
    }

    #pragma unroll
    for (int r = 0; r < 8; r++) {
        float* dst = g_T + (size_t)(rb * 64 + ty * 8 + r) * 4096 + cb * 256;
        float2 a0 = unpk(acc[r][0]), a1 = unpk(acc[r][1]);
        float2 a2 = unpk(acc[r][2]), a3 = unpk(acc[r][3]);
        reinterpret_cast<float4*>(dst + tx * 4)[0] = make_float4(a0.x, a0.y, a1.x, a1.y);
        reinterpret_cast<float4*>(dst + 128 + tx * 4)[0] = make_float4(a2.x, a2.y, a3.x, a3.y);
    }
}

// ---------------------------------------------------------------------------
// Stage D: out[row, j, o] = sum_d2 T[row][d2][o] * Y[b][j][d2] + bc[o]
// Block = (row, j-tile of 256). 256 threads, each 8j x 8o.
//  - tdup[d2][128]: T values duplicated {t,t} -> inner loop loads broadcast
//    pairs with plain LDS.128, zero mov.b64 broadcasts.
//  - ys[d2][256]: Y transposed; ulonglong2 loads give j-pairs directly.
//  - acc[jp][q] (f32x2) packs {out[j0][o], out[j1][o]}.
// Issue mix per d2 per thread: 6 LDS.128 + 32 fma2 (1.19 slots/fma2).
// 96KB smem -> 2 blocks/SM, 4 warps/SMSP.
// ---------------------------------------------------------------------------
__global__ void __launch_bounds__(256, 2) out_fast(const float* __restrict__ bc,
                                                   float* __restrict__ out)
{
    float* tdup = reinterpret_cast<float*>(dyn_smem);   // [64][128]  32KB
    float* ys   = tdup + 64 * 128;                      // [64][256]  64KB

    const int blk = blockIdx.x;      // 0..4095
    const int jt  = blk & 1;         // j tile (256 each)
    const int row = blk >> 1;        // b*512 + i
    const int b   = row >> 9;
    const int tid = threadIdx.x;

    // Fill tdup from g_T[row] ([d2][o], 4096 floats): duplicate each value.
    {
        const float4* src = reinterpret_cast<const float4*>(g_T + (size_t)row * 4096);
        #pragma unroll
        for (int it = 0; it < 4; it++) {
            int idx4 = it * 256 + tid;          // 0..1023 float4s
            float4 v = src[idx4];
            int d2 = idx4 >> 4;
            int o  = (idx4 & 15) * 4;
            float2* d = reinterpret_cast<float2*>(tdup + d2 * 128 + o * 2);
            d[0] = make_float2(v.x, v.x);
            d[1] = make_float2(v.y, v.y);
            d[2] = make_float2(v.z, v.z);
            d[3] = make_float2(v.w, v.w);
        }
    }
    // Fill ys transposed: thread owns local j row = tid (conflict-free STS)
    {
        const float4* src =
            reinterpret_cast<const float4*>(g_Y + (size_t)(b * 512 + jt * 256 + tid) * 64);
        #pragma unroll
        for (int c4 = 0; c4 < 16; c4++) {
            float4 v = src[c4];
            ys[(4 * c4 + 0) * 256 + tid] = v.x;
            ys[(4 * c4 + 1) * 256 + tid] = v.y;
            ys[(4 * c4 + 2) * 256 + tid] = v.z;
            ys[(4 * c4 + 3) * 256 + tid] = v.w;
        }
    }
    __syncthreads();

    const int tx = tid & 7;    // o: pairs (c*16 + tx*2 + p), c=0..3, p=0..1
    const int ty = tid >> 3;   // j: local rows ty*8 .. ty*8+7

    unsigned long long acc[4][8];   // [j-pair][o-slot]
    #pragma unroll
    for (int r = 0; r < 4; r++)
        #pragma unroll
        for (int q = 0; q < 8; q++) acc[r][q] = 0ull;

    #pragma unroll 4
    for (int d2 = 0; d2 < 64; d2++) {
        const float* tr = tdup + d2 * 128;
        ulonglong2 t0 = *reinterpret_cast<const ulonglong2*>(tr + tx * 4);
        ulonglong2 t1 = *reinterpret_cast<const ulonglong2*>(tr + 32 + tx * 4);
        ulonglong2 t2 = *reinterpret_cast<const ulonglong2*>(tr + 64 + tx * 4);
        ulonglong2 t3 = *reinterpret_cast<const ulonglong2*>(tr + 96 + tx * 4);
        unsigned long long tv[8] = {t0.x, t0.y, t1.x, t1.y, t2.x, t2.y, t3.x, t3.y};
        const float* yr = ys + d2 * 256 + ty * 8;
        ulonglong2 ya = *reinterpret_cast<const ulonglong2*>(yr);
        ulonglong2 yb = *reinterpret_cast<const ulonglong2*>(yr + 4);
        unsigned long long yv[4] = {ya.x, ya.y, yb.x, yb.y};
        #pragma unroll
        for (int r = 0; r < 4; r++)
            #pragma unroll
            for (int q = 0; q < 8; q++) fma2(acc[r][q], yv[r], tv[q]);
    }

    // bias for this thread's 8 o values
    float bv[8];
    #pragma unroll
    for (int c = 0; c < 4; c++) {
        bv[c * 2 + 0] = __ldg(bc + c * 16 + tx * 2 + 0);
        bv[c * 2 + 1] = __ldg(bc + c * 16 + tx * 2 + 1);
    }

    // Epilogue: acc[r][c*2+p] = {out[j_even][o], out[j_odd][o]}, o = c*16+tx*2+p
    #pragma unroll
    for (int r = 0; r < 4; r++) {
        float2 u[8];
        #pragma unroll
        for (int q = 0; q < 8; q++) u[q] = unpk(acc[r][q]);
        #pragma unroll
        for (int e = 0; e < 2; e++) {
            int j = jt * 256 + ty * 8 + r * 2 + e;
            float* dst = out + ((size_t)row * 512 + j) * 64;
            #pragma unroll
            for (int c = 0; c < 4; c++) {
                float v0 = (e ? u[c * 2 + 0].y : u[c * 2 + 0].x) + bv[c * 2 + 0];
                float v1 = (e ? u[c * 2 + 1].y : u[c * 2 + 1].x) + bv[c * 2 + 1];
                *reinterpret_cast<float2*>(dst + c * 16 + tx * 2) = make_float2(v0, v1);
            }
        }
    }
}

// ---------------------------------------------------------------------------
extern "C" void kernel_launch(void* const* d_in, const int* in_sizes, int n_in,
                              void* d_out, int out_size)
{
    const float* emb  = (const float*)d_in[0];
    /* d_in[1] = node_mask, unused */
    const float* ln_g = (const float*)d_in[2];
    const float* ln_b = (const float*)d_in[3];
    const float* W1   = (const float*)d_in[4];
    const float* b1   = (const float*)d_in[5];
    const float* W2   = (const float*)d_in[6];
    const float* b2   = (const float*)d_in[7];
    const float* Wc   = (const float*)d_in[8];
    const float* bc   = (const float*)d_in[9];
    float* out = (float*)d_out;

    const int smemB = (64 * 64 + 64 * 256) * sizeof(float);   // 81920
    const int smemD = (64 * 128 + 64 * 256) * sizeof(float);  // 98304
    cudaFuncSetAttribute(t_kernel, cudaFuncAttributeMaxDynamicSharedMemorySize, smemB);
    cudaFuncSetAttribute(out_fast, cudaFuncAttributeMaxDynamicSharedMemorySize, smemD);

    prep_kernel<<<NROWS, 64>>>(emb, ln_g, ln_b, W1, b1, W2, b2);
    wt_kernel<<<(EDIM * CDIM) / 256, 256>>>(Wc);
    {
        dim3 grid(16, 32);      // 16 col blocks x 32 row blocks
        t_kernel<<<grid, 256, smemB>>>();
    }
    out_fast<<<NROWS * 2, 256, smemD>>>(bc, out);
}

// round 15
// speedup vs baseline: 1.0004x; 1.0004x over previous
#include <cuda_runtime.h>
#include <cstdint>

// Problem constants: B=4, N=512, E=64
#define NROWS 2048          // B*N
#define EDIM  64
#define CDIM  4096          // E*E

// Single dynamic shared memory symbol (shared across all kernels in this TU)
extern __shared__ char dyn_smem[];

// Scratch
__device__ float g_X[NROWS * EDIM];   // left gated activations  [row][d1]
__device__ float g_Y[NROWS * EDIM];   // right gated activations [row][d2]
__device__ float g_Wt[EDIM * CDIM];   // Wt[d1][d2*64+o] = Wc[o][d1*64+d2]
__device__ float g_T[NROWS * CDIM];   // T[row][d2*64+o]

// ---------------------------------------------------------------------------
// Packed fp32x2 helpers
// ---------------------------------------------------------------------------
__device__ __forceinline__ unsigned long long bcast2(float x) {
    unsigned long long r;
    asm("mov.b64 %0, {%1, %1};" : "=l"(r) : "f"(x));
    return r;
}
__device__ __forceinline__ void fma2(unsigned long long& d,
                                     unsigned long long a,
                                     unsigned long long b) {
    asm("fma.rn.f32x2 %0, %1, %2, %3;" : "=l"(d) : "l"(a), "l"(b), "l"(d));
}
__device__ __forceinline__ float2 unpk(unsigned long long v) {
    float2 f;
    asm("mov.b64 {%0, %1}, %2;" : "=f"(f.x), "=f"(f.y) : "l"(v));
    return f;
}

// ---------------------------------------------------------------------------
// Stage A: LayerNorm + two gated projections. 1 block per row, 64 threads.
// ---------------------------------------------------------------------------
__global__ void prep_kernel(const float* __restrict__ emb,
                            const float* __restrict__ g,
                            const float* __restrict__ be,
                            const float* __restrict__ W1,
                            const float* __restrict__ b1,
                            const float* __restrict__ W2,
                            const float* __restrict__ b2)
{
    __shared__ float hsh[64];
    __shared__ float w1s[64 * 65];
    __shared__ float w2s[64 * 65];

    const int row = blockIdx.x;
    const int t   = threadIdx.x;

    for (int i = 0; i < 64; i++) {
        w1s[t * 65 + i] = W1[i * 64 + t];
        w2s[t * 65 + i] = W2[i * 64 + t];
    }

    float v = emb[row * 64 + t];
    hsh[t] = v;
    __syncthreads();

    float s = 0.f;
    #pragma unroll
    for (int d = 0; d < 64; d++) s += hsh[d];
    float mu = s * (1.0f / 64.0f);

    float vs = 0.f;
    #pragma unroll
    for (int d = 0; d < 64; d++) { float z = hsh[d] - mu; vs += z * z; }
    float rstd = rsqrtf(vs * (1.0f / 64.0f) + 1e-5f);

    float h = (v - mu) * rstd * g[t] + be[t];
    __syncthreads();
    hsh[t] = h;
    __syncthreads();

    float p1 = b1[t], p2 = b2[t];
    #pragma unroll
    for (int d = 0; d < 64; d++) {
        float hd = hsh[d];
        p1 += hd * w1s[d * 65 + t];
        p2 += hd * w2s[d * 65 + t];
    }
    g_X[row * 64 + t] = h * p1;
    g_Y[row * 64 + t] = h * p2;
}

// ---------------------------------------------------------------------------
// Stage C: Wt[d1*4096 + d2*64 + o] = Wc[o*4096 + d1*64 + d2]
// ---------------------------------------------------------------------------
__global__ void wt_kernel(const float* __restrict__ Wc)
{
    int i = blockIdx.x * blockDim.x + threadIdx.x;   // 0 .. 262143
    int o    = i & 63;
    int rest = i >> 6;          // d1*64 + d2
    g_Wt[i] = Wc[o * 4096 + rest];
}

// ---------------------------------------------------------------------------
// Stage B: T = X @ Wt  ([2048 x 64] * [64 x 4096]) -> g_T[row][d2*64+o]
// Packed f32x2 accumulation (R9 version, passing).
// ---------------------------------------------------------------------------
__global__ void __launch_bounds__(256) t_kernel()
{
    float* smem = reinterpret_cast<float*>(dyn_smem);
    float* xs = smem;             // [64 d1][64 r]
    float* ws = smem + 64 * 64;   // [64 d1][256 c]

    const int cb  = blockIdx.x;
    const int rb  = blockIdx.y;
    const int tid = threadIdx.x;

    if (tid < 64) {
        const float4* src = reinterpret_cast<const float4*>(g_X + (rb * 64 + tid) * 64);
        #pragma unroll
        for (int c4 = 0; c4 < 16; c4++) {
            float4 v = src[c4];
            xs[(4 * c4 + 0) * 64 + tid] = v.x;
            xs[(4 * c4 + 1) * 64 + tid] = v.y;
            xs[(4 * c4 + 2) * 64 + tid] = v.z;
            xs[(4 * c4 + 3) * 64 + tid] = v.w;
        }
    }
    #pragma unroll
    for (int it = 0; it < 16; it++) {
        int idx = it * 256 + tid;
        int d1  = idx >> 6;
        int c4  = idx & 63;
        reinterpret_cast<float4*>(ws + d1 * 256)[c4] =
            reinterpret_cast<const float4*>(g_Wt + d1 * 4096 + cb * 256)[c4];
    }
    __syncthreads();

    const int tx = tid & 31;
    const int ty = tid >> 5;

    unsigned long long acc[8][4];
    #pragma unroll
    for (int r = 0; r < 8; r++)
        #pragma unroll
        for (int p = 0; p < 4; p++) acc[r][p] = 0ull;

    #pragma unroll 4
    for (int d1 = 0; d1 < 64; d1++) {
        const float* xrow = xs + d1 * 64 + ty * 8;
        float4 a0 = reinterpret_cast<const float4*>(xrow)[0];
        float4 a1 = reinterpret_cast<const float4*>(xrow)[1];
        const float* wrow = ws + d1 * 256;
        ulonglong2 wA = *reinterpret_cast<const ulonglong2*>(wrow + tx * 4);
        ulonglong2 wB = *reinterpret_cast<const ulonglong2*>(wrow + 128 + tx * 4);
        unsigned long long tv[4] = {wA.x, wA.y, wB.x, wB.y};
        float av[8] = {a0.x, a0.y, a0.z, a0.w, a1.x, a1.y, a1.z, a1.w};
        #pragma unroll
        for (int r = 0; r < 8; r++) {
            unsigned long long yb = bcast2(av[r]);
            #pragma unroll
            for (int p = 0; p < 4; p++) fma2(acc[r][p], yb, tv[p]);
        }
    }

    #pragma unroll
    for (int r = 0; r < 8; r++) {
        float* dst = g_T + (size_t)(rb * 64 + ty * 8 + r) * 4096 + cb * 256;
        float2 a0 = unpk(acc[r][0]), a1 = unpk(acc[r][1]);
        float2 a2 = unpk(acc[r][2]), a3 = unpk(acc[r][3]);
        reinterpret_cast<float4*>(dst + tx * 4)[0] = make_float4(a0.x, a0.y, a1.x, a1.y);
        reinterpret_cast<float4*>(dst + 128 + tx * 4)[0] = make_float4(a2.x, a2.y, a3.x, a3.y);
    }
}

// ---------------------------------------------------------------------------
// Stage D: out[row, j, o] = sum_d2 T[row][d2][o] * Y[b][j][d2] + bc[o]
// Block = (row, j-tile of 256). 256 threads, each 8j x 8o.
//  - tdup[d2][128]: T values duplicated {t,t} -> inner loop loads broadcast
//    pairs with plain LDS.128, zero mov.b64 broadcasts.
//  - ys[d2][256]: Y transposed; ulonglong2 loads give j-pairs directly.
//  - acc[jp][q] (f32x2) packs {out[j0][o], out[j1][o]}.
// Issue mix per d2 per thread: 6 LDS.128 + 32 fma2 (1.19 slots/fma2).
// 96KB smem -> 2 blocks/SM, 4 warps/SMSP.
// ---------------------------------------------------------------------------
__global__ void __launch_bounds__(256, 2) out_fast(const float* __restrict__ bc,
                                                   float* __restrict__ out)
{
    float* tdup = reinterpret_cast<float*>(dyn_smem);   // [64][128]  32KB
    float* ys   = tdup + 64 * 128;                      // [64][256]  64KB

    const int blk = blockIdx.x;      // 0..4095
    const int jt  = blk & 1;         // j tile (256 each)
    const int row = blk >> 1;        // b*512 + i
    const int b   = row >> 9;
    const int tid = threadIdx.x;

    // Fill tdup from g_T[row] ([d2][o], 4096 floats): duplicate each value.
    {
        const float4* src = reinterpret_cast<const float4*>(g_T + (size_t)row * 4096);
        #pragma unroll
        for (int it = 0; it < 4; it++) {
            int idx4 = it * 256 + tid;          // 0..1023 float4s
            float4 v = src[idx4];
            int d2 = idx4 >> 4;
            int o  = (idx4 & 15) * 4;
            float2* d = reinterpret_cast<float2*>(tdup + d2 * 128 + o * 2);
            d[0] = make_float2(v.x, v.x);
            d[1] = make_float2(v.y, v.y);
            d[2] = make_float2(v.z, v.z);
            d[3] = make_float2(v.w, v.w);
        }
    }
    // Fill ys transposed: thread owns local j row = tid (conflict-free STS)
    {
        const float4* src =
            reinterpret_cast<const float4*>(g_Y + (size_t)(b * 512 + jt * 256 + tid) * 64);
        #pragma unroll
        for (int c4 = 0; c4 < 16; c4++) {
            float4 v = src[c4];
            ys[(4 * c4 + 0) * 256 + tid] = v.x;
            ys[(4 * c4 + 1) * 256 + tid] = v.y;
            ys[(4 * c4 + 2) * 256 + tid] = v.z;
            ys[(4 * c4 + 3) * 256 + tid] = v.w;
        }
    }
    __syncthreads();

    const int tx = tid & 7;    // o: pairs (c*16 + tx*2 + p), c=0..3, p=0..1
    const int ty = tid >> 3;   // j: local rows ty*8 .. ty*8+7

    unsigned long long acc[4][8];   // [j-pair][o-slot]
    #pragma unroll
    for (int r = 0; r < 4; r++)
        #pragma unroll
        for (int q = 0; q < 8; q++) acc[r][q] = 0ull;

    #pragma unroll 4
    for (int d2 = 0; d2 < 64; d2++) {
        const float* tr = tdup + d2 * 128;
        ulonglong2 t0 = *reinterpret_cast<const ulonglong2*>(tr + tx * 4);
        ulonglong2 t1 = *reinterpret_cast<const ulonglong2*>(tr + 32 + tx * 4);
        ulonglong2 t2 = *reinterpret_cast<const ulonglong2*>(tr + 64 + tx * 4);
        ulonglong2 t3 = *reinterpret_cast<const ulonglong2*>(tr + 96 + tx * 4);
        unsigned long long tv[8] = {t0.x, t0.y, t1.x, t1.y, t2.x, t2.y, t3.x, t3.y};
        const float* yr = ys + d2 * 256 + ty * 8;
        ulonglong2 ya = *reinterpret_cast<const ulonglong2*>(yr);
        ulonglong2 yb = *reinterpret_cast<const ulonglong2*>(yr + 4);
        unsigned long long yv[4] = {ya.x, ya.y, yb.x, yb.y};
        #pragma unroll
        for (int r = 0; r < 4; r++)
            #pragma unroll
            for (int q = 0; q < 8; q++) fma2(acc[r][q], yv[r], tv[q]);
    }

    // bias for this thread's 8 o values
    float bv[8];
    #pragma unroll
    for (int c = 0; c < 4; c++) {
        bv[c * 2 + 0] = __ldg(bc + c * 16 + tx * 2 + 0);
        bv[c * 2 + 1] = __ldg(bc + c * 16 + tx * 2 + 1);
    }

    // Epilogue: acc[r][c*2+p] = {out[j_even][o], out[j_odd][o]}, o = c*16+tx*2+p
    #pragma unroll
    for (int r = 0; r < 4; r++) {
        float2 u[8];
        #pragma unroll
        for (int q = 0; q < 8; q++) u[q] = unpk(acc[r][q]);
        #pragma unroll
        for (int e = 0; e < 2; e++) {
            int j = jt * 256 + ty * 8 + r * 2 + e;
            float* dst = out + ((size_t)row * 512 + j) * 64;
            #pragma unroll
            for (int c = 0; c < 4; c++) {
                float v0 = (e ? u[c * 2 + 0].y : u[c * 2 + 0].x) + bv[c * 2 + 0];
                float v1 = (e ? u[c * 2 + 1].y : u[c * 2 + 1].x) + bv[c * 2 + 1];
                *reinterpret_cast<float2*>(dst + c * 16 + tx * 2) = make_float2(v0, v1);
            }
        }
    }
}

// ---------------------------------------------------------------------------
extern "C" void kernel_launch(void* const* d_in, const int* in_sizes, int n_in,
                              void* d_out, int out_size)
{
    const float* emb  = (const float*)d_in[0];
    /* d_in[1] = node_mask, unused */
    const float* ln_g = (const float*)d_in[2];
    const float* ln_b = (const float*)d_in[3];
    const float* W1   = (const float*)d_in[4];
    const float* b1   = (const float*)d_in[5];
    const float* W2   = (const float*)d_in[6];
    const float* b2   = (const float*)d_in[7];
    const float* Wc   = (const float*)d_in[8];
    const float* bc   = (const float*)d_in[9];
    float* out = (float*)d_out;

    const int smemB = (64 * 64 + 64 * 256) * sizeof(float);   // 81920
    const int smemD = (64 * 128 + 64 * 256) * sizeof(float);  // 98304
    cudaFuncSetAttribute(t_kernel, cudaFuncAttributeMaxDynamicSharedMemorySize, smemB);
    cudaFuncSetAttribute(out_fast, cudaFuncAttributeMaxDynamicSharedMemorySize, smemD);

    prep_kernel<<<NROWS, 64>>>(emb, ln_g, ln_b, W1, b1, W2, b2);
    wt_kernel<<<(EDIM * CDIM) / 256, 256>>>(Wc);
    {
        dim3 grid(16, 32);      // 16 col blocks x 32 row blocks
        t_kernel<<<grid, 256, smemB>>>();
    }
    out_fast<<<NROWS * 2, 256, smemD>>>(bc, out);
}

// round 16
// speedup vs baseline: 1.0017x; 1.0012x over previous
#include <cuda_runtime.h>
#include <cstdint>

// Problem constants: B=4, N=512, E=64
#define NROWS 2048          // B*N
#define EDIM  64
#define CDIM  4096          // E*E

// Single dynamic shared memory symbol (shared across all kernels in this TU)
extern __shared__ char dyn_smem[];

// Scratch
__device__ float g_X[NROWS * EDIM];   // left gated activations  [row][d1]
__device__ float g_Y[NROWS * EDIM];   // right gated activations [row][d2]
__device__ float g_Wt[EDIM * CDIM];   // Wt[d1][d2*64+o] = Wc[o][d1*64+d2]
__device__ float g_T[NROWS * CDIM];   // T[row][d2*64+o]

// ---------------------------------------------------------------------------
// Packed fp32x2 helpers
// ---------------------------------------------------------------------------
__device__ __forceinline__ unsigned long long bcast2(float x) {
    unsigned long long r;
    asm("mov.b64 %0, {%1, %1};" : "=l"(r) : "f"(x));
    return r;
}
__device__ __forceinline__ void fma2(unsigned long long& d,
                                     unsigned long long a,
                                     unsigned long long b) {
    asm("fma.rn.f32x2 %0, %1, %2, %3;" : "=l"(d) : "l"(a), "l"(b), "l"(d));
}
__device__ __forceinline__ float2 unpk(unsigned long long v) {
    float2 f;
    asm("mov.b64 {%0, %1}, %2;" : "=f"(f.x), "=f"(f.y) : "l"(v));
    return f;
}

// ---------------------------------------------------------------------------
// Stage A: LayerNorm + two gated projections. 1 block per row, 64 threads.
// ---------------------------------------------------------------------------
__global__ void prep_kernel(const float* __restrict__ emb,
                            const float* __restrict__ g,
                            const float* __restrict__ be,
                            const float* __restrict__ W1,
                            const float* __restrict__ b1,
                            const float* __restrict__ W2,
                            const float* __restrict__ b2)
{
    __shared__ float hsh[64];
    __shared__ float w1s[64 * 65];
    __shared__ float w2s[64 * 65];

    const int row = blockIdx.x;
    const int t   = threadIdx.x;

    for (int i = 0; i < 64; i++) {
        w1s[t * 65 + i] = W1[i * 64 + t];
        w2s[t * 65 + i] = W2[i * 64 + t];
    }

    float v = emb[row * 64 + t];
    hsh[t] = v;
    __syncthreads();

    float s = 0.f;
    #pragma unroll
    for (int d = 0; d < 64; d++) s += hsh[d];
    float mu = s * (1.0f / 64.0f);

    float vs = 0.f;
    #pragma unroll
    for (int d = 0; d < 64; d++) { float z = hsh[d] - mu; vs += z * z; }
    float rstd = rsqrtf(vs * (1.0f / 64.0f) + 1e-5f);

    float h = (v - mu) * rstd * g[t] + be[t];
    __syncthreads();
    hsh[t] = h;
    __syncthreads();

    float p1 = b1[t], p2 = b2[t];
    #pragma unroll
    for (int d = 0; d < 64; d++) {
        float hd = hsh[d];
        p1 += hd * w1s[d * 65 + t];
        p2 += hd * w2s[d * 65 + t];
    }
    g_X[row * 64 + t] = h * p1;
    g_Y[row * 64 + t] = h * p2;
}

// ---------------------------------------------------------------------------
// Stage C: Wt[d1*4096 + d2*64 + o] = Wc[o*4096 + d1*64 + d2]
// ---------------------------------------------------------------------------
__global__ void wt_kernel(const float* __restrict__ Wc)
{
    int i = blockIdx.x * blockDim.x + threadIdx.x;   // 0 .. 262143
    int o    = i & 63;
    int rest = i >> 6;          // d1*64 + d2
    g_Wt[i] = Wc[o * 4096 + rest];
}

// ---------------------------------------------------------------------------
// Stage B: T = X @ Wt  ([2048 x 64] * [64 x 4096]) -> g_T[row][d2*64+o]
// Packed f32x2 accumulation (R9 version, passing).
// ---------------------------------------------------------------------------
__global__ void __launch_bounds__(256) t_kernel()
{
    float* smem = reinterpret_cast<float*>(dyn_smem);
    float* xs = smem;             // [64 d1][64 r]
    float* ws = smem + 64 * 64;   // [64 d1][256 c]

    const int cb  = blockIdx.x;
    const int rb  = blockIdx.y;
    const int tid = threadIdx.x;

    if (tid < 64) {
        const float4* src = reinterpret_cast<const float4*>(g_X + (rb * 64 + tid) * 64);
        #pragma unroll
        for (int c4 = 0; c4 < 16; c4++) {
            float4 v = src[c4];
            xs[(4 * c4 + 0) * 64 + tid] = v.x;
            xs[(4 * c4 + 1) * 64 + tid] = v.y;
            xs[(4 * c4 + 2) * 64 + tid] = v.z;
            xs[(4 * c4 + 3) * 64 + tid] = v.w;
        }
    }
    #pragma unroll
    for (int it = 0; it < 16; it++) {
        int idx = it * 256 + tid;
        int d1  = idx >> 6;
        int c4  = idx & 63;
        reinterpret_cast<float4*>(ws + d1 * 256)[c4] =
            reinterpret_cast<const float4*>(g_Wt + d1 * 4096 + cb * 256)[c4];
    }
    __syncthreads();

    const int tx = tid & 31;
    const int ty = tid >> 5;

    unsigned long long acc[8][4];
    #pragma unroll
    for (int r = 0; r < 8; r++)
        #pragma unroll
        for (int p = 0; p < 4; p++) acc[r][p] = 0ull;

    #pragma unroll 4
    for (int d1 = 0; d1 < 64; d1++) {
        const float* xrow = xs + d1 * 64 + ty * 8;
        float4 a0 = reinterpret_cast<const float4*>(xrow)[0];
        float4 a1 = reinterpret_cast<const float4*>(xrow)[1];
        const float* wrow = ws + d1 * 256;
        ulonglong2 wA = *reinterpret_cast<const ulonglong2*>(wrow + tx * 4);
        ulonglong2 wB = *reinterpret_cast<const ulonglong2*>(wrow + 128 + tx * 4);
        unsigned long long tv[4] = {wA.x, wA.y, wB.x, wB.y};
        float av[8] = {a0.x, a0.y, a0.z, a0.w, a1.x, a1.y, a1.z, a1.w};
        #pragma unroll
        for (int r = 0; r < 8; r++) {
            unsigned long long yb = bcast2(av[r]);
            #pragma unroll
            for (int p = 0; p < 4; p++) fma2(acc[r][p], yb, tv[p]);
        }
    }

    #pragma unroll
    for (int r = 0; r < 8; r++) {
        float* dst = g_T + (size_t)(rb * 64 + ty * 8 + r) * 4096 + cb * 256;
        float2 a0 = unpk(acc[r][0]), a1 = unpk(acc[r][1]);
        float2 a2 = unpk(acc[r][2]), a3 = unpk(acc[r][3]);
        reinterpret_cast<float4*>(dst + tx * 4)[0] = make_float4(a0.x, a0.y, a1.x, a1.y);
        reinterpret_cast<float4*>(dst + 128 + tx * 4)[0] = make_float4(a2.x, a2.y, a3.x, a3.y);
    }
}

// ---------------------------------------------------------------------------
// Stage D: out[row, j, o] = sum_d2 T[row][d2][o] * Y[b][j][d2] + bc[o]
// Block = (row, j-tile of 256). 256 threads, each 8j x 8o.
//  - tdup[d2][128]: T values duplicated {t,t} -> inner loop loads broadcast
//    pairs with plain LDS.128, zero mov.b64 broadcasts.
//  - ys[d2][256]: Y transposed; ulonglong2 loads give j-pairs directly.
//  - acc[jp][q] (f32x2) packs {out[j0][o], out[j1][o]}.
// Issue mix per d2 per thread: 6 LDS.128 + 32 fma2 (1.19 slots/fma2).
// 96KB smem -> 2 blocks/SM, 4 warps/SMSP.
// ---------------------------------------------------------------------------
__global__ void __launch_bounds__(256, 2) out_fast(const float* __restrict__ bc,
                                                   float* __restrict__ out)
{
    float* tdup = reinterpret_cast<float*>(dyn_smem);   // [64][128]  32KB
    float* ys   = tdup + 64 * 128;                      // [64][256]  64KB

    const int blk = blockIdx.x;      // 0..4095
    const int jt  = blk & 1;         // j tile (256 each)
    const int row = blk >> 1;        // b*512 + i
    const int b   = row >> 9;
    const int tid = threadIdx.x;

    // Fill tdup from g_T[row] ([d2][o], 4096 floats): duplicate each value.
    {
        const float4* src = reinterpret_cast<const float4*>(g_T + (size_t)row * 4096);
        #pragma unroll
        for (int it = 0; it < 4; it++) {
            int idx4 = it * 256 + tid;          // 0..1023 float4s
            float4 v = src[idx4];
            int d2 = idx4 >> 4;
            int o  = (idx4 & 15) * 4;
            float2* d = reinterpret_cast<float2*>(tdup + d2 * 128 + o * 2);
            d[0] = make_float2(v.x, v.x);
            d[1] = make_float2(v.y, v.y);
            d[2] = make_float2(v.z, v.z);
            d[3] = make_float2(v.w, v.w);
        }
    }
    // Fill ys transposed: thread owns local j row = tid (conflict-free STS)
    {
        const float4* src =
            reinterpret_cast<const float4*>(g_Y + (size_t)(b * 512 + jt * 256 + tid) * 64);
        #pragma unroll
        for (int c4 = 0; c4 < 16; c4++) {
            float4 v = src[c4];
            ys[(4 * c4 + 0) * 256 + tid] = v.x;
            ys[(4 * c4 + 1) * 256 + tid] = v.y;
            ys[(4 * c4 + 2) * 256 + tid] = v.z;
            ys[(4 * c4 + 3) * 256 + tid] = v.w;
        }
    }
    __syncthreads();

    const int tx = tid & 7;    // o: pairs (c*16 + tx*2 + p), c=0..3, p=0..1
    const int ty = tid >> 3;   // j: local rows ty*8 .. ty*8+7

    unsigned long long acc[4][8];   // [j-pair][o-slot]
    #pragma unroll
    for (int r = 0; r < 4; r++)
        #pragma unroll
        for (int q = 0; q < 8; q++) acc[r][q] = 0ull;

    #pragma unroll 4
    for (int d2 = 0; d2 < 64; d2++) {
        const float* tr = tdup + d2 * 128;
        ulonglong2 t0 = *reinterpret_cast<const ulonglong2*>(tr + tx * 4);
        ulonglong2 t1 = *reinterpret_cast<const ulonglong2*>(tr + 32 + tx * 4);
        ulonglong2 t2 = *reinterpret_cast<const ulonglong2*>(tr + 64 + tx * 4);
        ulonglong2 t3 = *reinterpret_cast<const ulonglong2*>(tr + 96 + tx * 4);
        unsigned long long tv[8] = {t0.x, t0.y, t1.x, t1.y, t2.x, t2.y, t3.x, t3.y};
        const float* yr = ys + d2 * 256 + ty * 8;
        ulonglong2 ya = *reinterpret_cast<const ulonglong2*>(yr);
        ulonglong2 yb = *reinterpret_cast<const ulonglong2*>(yr + 4);
        unsigned long long yv[4] = {ya.x, ya.y, yb.x, yb.y};
        #pragma unroll
        for (int r = 0; r < 4; r++)
            #pragma unroll
            for (int q = 0; q < 8; q++) fma2(acc[r][q], yv[r], tv[q]);
    }

    // bias for this thread's 8 o values
    float bv[8];
    #pragma unroll
    for (int c = 0; c < 4; c++) {
        bv[c * 2 + 0] = __ldg(bc + c * 16 + tx * 2 + 0);
        bv[c * 2 + 1] = __ldg(bc + c * 16 + tx * 2 + 1);
    }

    // Epilogue: acc[r][c*2+p] = {out[j_even][o], out[j_odd][o]}, o = c*16+tx*2+p
    #pragma unroll
    for (int r = 0; r < 4; r++) {
        float2 u[8];
        #pragma unroll
        for (int q = 0; q < 8; q++) u[q] = unpk(acc[r][q]);
        #pragma unroll
        for (int e = 0; e < 2; e++) {
            int j = jt * 256 + ty * 8 + r * 2 + e;
            float* dst = out + ((size_t)row * 512 + j) * 64;
            #pragma unroll
            for (int c = 0; c < 4; c++) {
                float v0 = (e ? u[c * 2 + 0].y : u[c * 2 + 0].x) + bv[c * 2 + 0];
                float v1 = (e ? u[c * 2 + 1].y : u[c * 2 + 1].x) + bv[c * 2 + 1];
                *reinterpret_cast<float2*>(dst + c * 16 + tx * 2) = make_float2(v0, v1);
            }
        }
    }
}

// ---------------------------------------------------------------------------
extern "C" void kernel_launch(void* const* d_in, const int* in_sizes, int n_in,
                              void* d_out, int out_size)
{
    const float* emb  = (const float*)d_in[0];
    /* d_in[1] = node_mask, unused */
    const float* ln_g = (const float*)d_in[2];
    const float* ln_b = (const float*)d_in[3];
    const float* W1   = (const float*)d_in[4];
    const float* b1   = (const float*)d_in[5];
    const float* W2   = (const float*)d_in[6];
    const float* b2   = (const float*)d_in[7];
    const float* Wc   = (const float*)d_in[8];
    const float* bc   = (const float*)d_in[9];
    float* out = (float*)d_out;

    const int smemB = (64 * 64 + 64 * 256) * sizeof(float);   // 81920
    const int smemD = (64 * 128 + 64 * 256) * sizeof(float);  // 98304
    cudaFuncSetAttribute(t_kernel, cudaFuncAttributeMaxDynamicSharedMemorySize, smemB);
    cudaFuncSetAttribute(out_fast, cudaFuncAttributeMaxDynamicSharedMemorySize, smemD);

    prep_kernel<<<NROWS, 64>>>(emb, ln_g, ln_b, W1, b1, W2, b2);
    wt_kernel<<<(EDIM * CDIM) / 256, 256>>>(Wc);
    {
        dim3 grid(16, 32);      // 16 col blocks x 32 row blocks
        t_kernel<<<grid, 256, smemB>>>();
    }
    out_fast<<<NROWS * 2, 256, smemD>>>(bc, out);
}